// round 4
// baseline (speedup 1.0000x reference)
#include <cuda_runtime.h>
#include <cuda_bf16.h>
#include <cstdint>

// ---------------------------------------------------------------------------
// GraphAutoencoder (sm_100 base): overlapped scatter ∥ x-GEMM, then n-GEMM
// (accumulating) and decoder. GEMMs: mma.sync bf16 two-term split, fp32 acc.
// ---------------------------------------------------------------------------

#define N_NODES_MAX 50000
#define IN_DIM      256
#define HID_DIM     512
#define OUT_DIM     256

// ------------------------------ scratch ------------------------------------
__device__ __align__(16) float g_neigh[N_NODES_MAX * IN_DIM];
__device__ float g_deg[N_NODES_MAX];
__device__ __align__(16) __nv_bfloat16 g_xh[N_NODES_MAX * IN_DIM];
__device__ __align__(16) __nv_bfloat16 g_xl[N_NODES_MAX * IN_DIM];
__device__ __align__(16) __nv_bfloat16 g_nh[N_NODES_MAX * IN_DIM];
__device__ __align__(16) __nv_bfloat16 g_nl[N_NODES_MAX * IN_DIM];
__device__ __align__(16) __nv_bfloat16 g_hh[N_NODES_MAX * HID_DIM];
__device__ __align__(16) __nv_bfloat16 g_hl[N_NODES_MAX * HID_DIM];
// packed B, row-major [K'][N]: seg0=hi, seg1=lo, seg2=hi (A: h,h,l)
__device__ __align__(16) __nv_bfloat16 g_Bx[768 * HID_DIM];
__device__ __align__(16) __nv_bfloat16 g_Bn[768 * HID_DIM];
__device__ __align__(16) __nv_bfloat16 g_Bdec[1536 * OUT_DIM];
__device__ __align__(16) float g_hfb[N_NODES_MAX * HID_DIM];

// --------------------------- asm helpers -----------------------------------
__device__ __forceinline__ uint32_t smem_u32(const void* p) {
    uint32_t a;
    asm("{ .reg .u64 t; cvta.to.shared.u64 t, %1; cvt.u32.u64 %0, t; }"
        : "=r"(a) : "l"(p));
    return a;
}
__device__ __forceinline__ void cp16(uint32_t dst, const void* src, uint32_t srcsize) {
    asm volatile("cp.async.cg.shared.global [%0], [%1], 16, %2;"
                 :: "r"(dst), "l"(src), "r"(srcsize) : "memory");
}
__device__ __forceinline__ void cp_commit() {
    asm volatile("cp.async.commit_group;" ::: "memory");
}
template <int N>
__device__ __forceinline__ void cp_wait() {
    asm volatile("cp.async.wait_group %0;" :: "n"(N) : "memory");
}
#define LDSM_X4(r0, r1, r2, r3, a) \
    asm volatile("ldmatrix.sync.aligned.m8n8.x4.shared.b16 {%0,%1,%2,%3}, [%4];" \
                 : "=r"(r0), "=r"(r1), "=r"(r2), "=r"(r3) : "r"(a))
#define LDSM_X4_T(r0, r1, r2, r3, a) \
    asm volatile("ldmatrix.sync.aligned.m8n8.x4.trans.shared.b16 {%0,%1,%2,%3}, [%4];" \
                 : "=r"(r0), "=r"(r1), "=r"(r2), "=r"(r3) : "r"(a))
#define MMA16816(c, a0, a1, a2, a3, b0, b1) \
    asm volatile("mma.sync.aligned.m16n8k16.row.col.f32.bf16.bf16.f32 " \
                 "{%0,%1,%2,%3}, {%4,%5,%6,%7}, {%8,%9}, {%0,%1,%2,%3};" \
                 : "+f"((c)[0]), "+f"((c)[1]), "+f"((c)[2]), "+f"((c)[3]) \
                 : "r"(a0), "r"(a1), "r"(a2), "r"(a3), "r"(b0), "r"(b1))

// ----------------------------- prep kernels --------------------------------
// x split + pack all three B matrices (stream 0 branch)
__global__ void prep_x_kernel(const float* __restrict__ x,
                              const float* __restrict__ Wself,
                              const float* __restrict__ Wneigh,
                              const float* __restrict__ Wdec, int M) {
    int i = blockIdx.x * blockDim.x + threadIdx.x;
    int nx = M * IN_DIM;
    if (i < nx) {
        float v = x[i];
        __nv_bfloat16 hi = __float2bfloat16(v);
        g_xh[i] = hi;
        g_xl[i] = __float2bfloat16(v - __bfloat162float(hi));
        return;
    }
    int j = i - nx;
    if (j < 768 * HID_DIM) {                 // Bx from Wself
        int kp = j >> 9, n = j & 511;
        int seg = kp >> 8, k = kp & 255;
        float w = Wself[k * HID_DIM + n];
        __nv_bfloat16 hi = __float2bfloat16(w);
        g_Bx[j] = (seg == 1) ? __float2bfloat16(w - __bfloat162float(hi)) : hi;
        return;
    }
    j -= 768 * HID_DIM;
    if (j < 768 * HID_DIM) {                 // Bn from Wneigh
        int kp = j >> 9, n = j & 511;
        int seg = kp >> 8, k = kp & 255;
        float w = Wneigh[k * HID_DIM + n];
        __nv_bfloat16 hi = __float2bfloat16(w);
        g_Bn[j] = (seg == 1) ? __float2bfloat16(w - __bfloat162float(hi)) : hi;
        return;
    }
    j -= 768 * HID_DIM;
    if (j < 1536 * OUT_DIM) {                // Bdec from Wdec
        int kp = j >> 8, n = j & 255;
        int seg = kp >> 9, k = kp & 511;
        float w = Wdec[k * OUT_DIM + n];
        __nv_bfloat16 hi = __float2bfloat16(w);
        g_Bdec[j] = (seg == 1) ? __float2bfloat16(w - __bfloat162float(hi)) : hi;
    }
}

// scatter with degree fused (stream A)
__global__ void scatter_kernel(const float* __restrict__ x,
                               const int* __restrict__ src,
                               const int* __restrict__ dst,
                               int n_edges) {
    const int CH = IN_DIM / 4;
    long long total = (long long)n_edges * CH;
    long long i = (long long)blockIdx.x * blockDim.x + threadIdx.x;
    if (i >= total) return;
    int e = (int)(i >> 6), c = (int)(i & 63);
    int s = src[e], d = dst[e];
    if (c == 0) atomicAdd(&g_deg[d], 1.0f);
    float4 v = reinterpret_cast<const float4*>(x)[(long long)s * CH + c];
    atomicAdd(reinterpret_cast<float4*>(g_neigh) + (long long)d * CH + c, v);
}

// neigh mean + split (inv folded in)
__global__ void nsplit_kernel(int M) {
    int i = blockIdx.x * blockDim.x + threadIdx.x;
    if (i >= M * IN_DIM) return;
    int r = i >> 8;
    float v = g_neigh[i] / fmaxf(g_deg[r], 1.0f);
    __nv_bfloat16 hi = __float2bfloat16(v);
    g_nh[i] = hi;
    g_nl[i] = __float2bfloat16(v - __bfloat162float(hi));
}

// ----------------------------- mma GEMM ------------------------------------
// CTA 128x128, 8 warps (4M x 2N), warp 32x64, BK=32, double buffered.
// A' = split-expanded A (3 segments of SEGK): [Ah | Ah | Al]
#define A_PITCH 80
#define B_PITCH 272
#define SZA (128 * A_PITCH)
#define SZB (32 * B_PITCH)

template <int SEGK, bool RELU, bool SPLIT, bool ACCIN, bool BIAS>
__global__ __launch_bounds__(256, 2)
void gemm_mma(const __nv_bfloat16* __restrict__ Ah,
              const __nv_bfloat16* __restrict__ Al,
              const __nv_bfloat16* __restrict__ Bp,
              const float* __restrict__ bias,
              float* __restrict__ C,
              __nv_bfloat16* __restrict__ oH, __nv_bfloat16* __restrict__ oL,
              int M, int N) {
    const int NCHUNK = 3 * SEGK / 32;
    const int CPS = SEGK / 32;               // chunks per segment
    __shared__ __align__(16) unsigned char smA[2 * SZA];
    __shared__ __align__(16) unsigned char smB[2 * SZB];
    uint32_t sA = smem_u32(smA), sB = smem_u32(smB);

    int tid = threadIdx.x;
    int wid = tid >> 5, lane = tid & 31;
    int wm = wid & 3, wn = wid >> 2;
    int rowBase = blockIdx.y * 128;
    int colBase = blockIdx.x * 128;

    float c[2][8][4];
#pragma unroll
    for (int f = 0; f < 2; f++)
#pragma unroll
        for (int nf = 0; nf < 8; nf++)
#pragma unroll
            for (int q = 0; q < 4; q++) c[f][nf][q] = 0.f;

    auto load_chunk = [&](int buf, int ch) {
        int seg = ch / CPS;
        const __nv_bfloat16* Asel = (seg < 2) ? Ah : Al;
        int k0 = (ch * 32) % SEGK;
        int kp0 = ch * 32;
#pragma unroll
        for (int i = 0; i < 2; i++) {
            int idx = tid + i * 256;
            int r = idx >> 2, cs = idx & 3;
            int grow = rowBase + r;
            int srow = grow < M ? grow : M - 1;
            cp16(sA + buf * SZA + r * A_PITCH + cs * 16,
                 Asel + (size_t)srow * SEGK + k0 + cs * 8,
                 grow < M ? 16u : 0u);
        }
#pragma unroll
        for (int i = 0; i < 2; i++) {
            int idx = tid + i * 256;
            int r = idx >> 4, cs = idx & 15;
            cp16(sB + buf * SZB + r * B_PITCH + cs * 16,
                 Bp + (size_t)(kp0 + r) * N + colBase + cs * 8, 16u);
        }
        cp_commit();
    };

    uint32_t aAddr = sA + (wm * 32 + (lane & 15)) * A_PITCH + (lane >> 4) * 16;
    uint32_t bAddr = sB + (lane & 15) * B_PITCH + wn * 128 + (lane >> 4) * 16;

    load_chunk(0, 0);
    for (int ch = 0; ch < NCHUNK; ch++) {
        int buf = ch & 1;
        if (ch + 1 < NCHUNK) { load_chunk(buf ^ 1, ch + 1); cp_wait<1>(); }
        else                 { cp_wait<0>(); }
        __syncthreads();

        uint32_t aB = aAddr + buf * SZA;
        uint32_t bB = bAddr + buf * SZB;
#pragma unroll
        for (int kk = 0; kk < 2; kk++) {
            uint32_t a[8];
            LDSM_X4(a[0], a[1], a[2], a[3], aB + kk * 32);
            LDSM_X4(a[4], a[5], a[6], a[7], aB + kk * 32 + 16 * A_PITCH);
            uint32_t b[16];
#pragma unroll
            for (int p = 0; p < 4; p++)
                LDSM_X4_T(b[4 * p], b[4 * p + 1], b[4 * p + 2], b[4 * p + 3],
                          bB + kk * 16 * B_PITCH + p * 32);
#pragma unroll
            for (int f = 0; f < 2; f++)
#pragma unroll
                for (int nf = 0; nf < 8; nf++) {
                    uint32_t* bp = b + (nf >> 1) * 4 + (nf & 1) * 2;
                    MMA16816(c[f][nf], a[f * 4], a[f * 4 + 1], a[f * 4 + 2],
                             a[f * 4 + 3], bp[0], bp[1]);
                }
        }
        __syncthreads();
    }

    int groupID = lane >> 2, tid4 = lane & 3;
#pragma unroll
    for (int f = 0; f < 2; f++) {
        int r0 = rowBase + wm * 32 + f * 16 + groupID;
#pragma unroll
        for (int nf = 0; nf < 8; nf++) {
            int cb = colBase + wn * 64 + nf * 8 + tid4 * 2;
            float b0 = 0.f, b1 = 0.f;
            if (BIAS) { b0 = bias[cb]; b1 = bias[cb + 1]; }
#pragma unroll
            for (int h = 0; h < 2; h++) {
                int r = r0 + h * 8;
                if (r >= M) continue;
                float* cptr = C + (size_t)r * N + cb;
                float v0 = c[f][nf][2 * h + 0] + b0;
                float v1 = c[f][nf][2 * h + 1] + b1;
                if (ACCIN) {
                    float2 prev = *reinterpret_cast<const float2*>(cptr);
                    v0 += prev.x; v1 += prev.y;
                }
                if (RELU) { v0 = fmaxf(v0, 0.f); v1 = fmaxf(v1, 0.f); }
                *reinterpret_cast<float2*>(cptr) = make_float2(v0, v1);
                if (SPLIT) {
                    __nv_bfloat16 h0 = __float2bfloat16(v0);
                    __nv_bfloat16 h1 = __float2bfloat16(v1);
                    __nv_bfloat162 hv; hv.x = h0; hv.y = h1;
                    *reinterpret_cast<__nv_bfloat162*>(oH + (size_t)r * N + cb) = hv;
                    __nv_bfloat162 lv;
                    lv.x = __float2bfloat16(v0 - __bfloat162float(h0));
                    lv.y = __float2bfloat16(v1 - __bfloat162float(h1));
                    *reinterpret_cast<__nv_bfloat162*>(oL + (size_t)r * N + cb) = lv;
                }
            }
        }
    }
}

// ------------------------------ launch -------------------------------------
extern "C" void kernel_launch(void* const* d_in, const int* in_sizes, int n_in,
                              void* d_out, int out_size) {
    const float* x       = (const float*)d_in[0];
    const int*   src     = (const int*)d_in[1];
    const int*   dst     = (const int*)d_in[2];
    const float* W_self  = (const float*)d_in[3];
    const float* W_neigh = (const float*)d_in[4];
    const float* b_enc   = (const float*)d_in[5];
    const float* W_dec   = (const float*)d_in[6];
    const float* b_dec   = (const float*)d_in[7];

    int M  = in_sizes[0] / IN_DIM;
    int nE = in_sizes[1];

    float* out = (float*)d_out;
    float* h;
    if (out_size == M * (OUT_DIM + HID_DIM)) {
        h = out + (long long)M * OUT_DIM;
    } else {
        void* p = nullptr;
        cudaGetSymbolAddress(&p, g_hfb);
        h = (float*)p;
    }

    void *p_xh, *p_xl, *p_nh, *p_nl, *p_hh, *p_hl, *p_bx, *p_bn, *p_bd;
    void *p_neigh, *p_deg;
    cudaGetSymbolAddress(&p_xh, g_xh);   cudaGetSymbolAddress(&p_xl, g_xl);
    cudaGetSymbolAddress(&p_nh, g_nh);   cudaGetSymbolAddress(&p_nl, g_nl);
    cudaGetSymbolAddress(&p_hh, g_hh);   cudaGetSymbolAddress(&p_hl, g_hl);
    cudaGetSymbolAddress(&p_bx, g_Bx);   cudaGetSymbolAddress(&p_bn, g_Bn);
    cudaGetSymbolAddress(&p_bd, g_Bdec);
    cudaGetSymbolAddress(&p_neigh, g_neigh);
    cudaGetSymbolAddress(&p_deg, g_deg);

    // One-time stream/event setup (outside capture on the correctness call).
    static cudaStream_t sA = nullptr;
    static cudaEvent_t ev0 = nullptr, evA = nullptr;
    if (!sA) {
        cudaStreamCreateWithFlags(&sA, cudaStreamNonBlocking);
        cudaEventCreateWithFlags(&ev0, cudaEventDisableTiming);
        cudaEventCreateWithFlags(&evA, cudaEventDisableTiming);
    }

    // ---- fork: stream A = scatter chain ----
    cudaEventRecord(ev0, 0);
    cudaStreamWaitEvent(sA, ev0, 0);
    cudaMemsetAsync(p_neigh, 0, (size_t)M * IN_DIM * sizeof(float), sA);
    cudaMemsetAsync(p_deg, 0, (size_t)M * sizeof(float), sA);
    {
        long long items = (long long)nE * (IN_DIM / 4);
        scatter_kernel<<<(int)((items + 255) / 256), 256, 0, sA>>>(x, src, dst, nE);
    }
    nsplit_kernel<<<(M * IN_DIM + 255) / 256, 256, 0, sA>>>(M);
    cudaEventRecord(evA, sA);

    // ---- stream 0 = x branch ----
    {
        int total = M * IN_DIM + 2 * 768 * HID_DIM + 1536 * OUT_DIM;
        prep_x_kernel<<<(total + 255) / 256, 256>>>(x, W_self, W_neigh, W_dec, M);
    }
    {   // x-part of encoder: h = xsplit @ Bx (raw partial)
        dim3 grid(HID_DIM / 128, (M + 127) / 128);
        gemm_mma<256, false, false, false, false><<<grid, 256>>>(
            (const __nv_bfloat16*)p_xh, (const __nv_bfloat16*)p_xl,
            (const __nv_bfloat16*)p_bx, nullptr, h, nullptr, nullptr, M, HID_DIM);
    }

    // ---- join ----
    cudaStreamWaitEvent(0, evA, 0);

    {   // n-part: h = relu(h + nsplit @ Bn + b_enc), emit h hi/lo
        dim3 grid(HID_DIM / 128, (M + 127) / 128);
        gemm_mma<256, true, true, true, true><<<grid, 256>>>(
            (const __nv_bfloat16*)p_nh, (const __nv_bfloat16*)p_nl,
            (const __nv_bfloat16*)p_bn, b_enc, h,
            (__nv_bfloat16*)p_hh, (__nv_bfloat16*)p_hl, M, HID_DIM);
    }
    {   // decoder: out = hsplit @ Bdec + b_dec
        dim3 grid(OUT_DIM / 128, (M + 127) / 128);
        gemm_mma<512, false, false, false, true><<<grid, 256>>>(
            (const __nv_bfloat16*)p_hh, (const __nv_bfloat16*)p_hl,
            (const __nv_bfloat16*)p_bd, b_dec, out, nullptr, nullptr, M, OUT_DIM);
    }
}

// round 5
// speedup vs baseline: 1.1029x; 1.1029x over previous
#include <cuda_runtime.h>
#include <cuda_bf16.h>
#include <cstdint>

// ---------------------------------------------------------------------------
// GraphAutoencoder (sm_100 base): scatter-mean -> encoder GEMM -> decoder GEMM
// R5: R3 structure + 3-stage cp.async pipeline (single sync per iteration).
// GEMMs: mma.sync bf16 two-term split (hh, h*lo, lo*h), fp32 acc, K'=1536.
// ---------------------------------------------------------------------------

#define N_NODES_MAX 50000
#define IN_DIM      256
#define HID_DIM     512
#define OUT_DIM     256
#define KP          1536
#define NCH         48           // KP / 32

// ------------------------------ scratch ------------------------------------
__device__ __align__(16) float g_neigh[N_NODES_MAX * IN_DIM];
__device__ float g_deg[N_NODES_MAX];
__device__ float g_inv[N_NODES_MAX];
__device__ __align__(16) __nv_bfloat16 g_eAh[N_NODES_MAX * 512];   // [x | nmean] hi
__device__ __align__(16) __nv_bfloat16 g_eAl[N_NODES_MAX * 512];   // [x | nmean] lo
__device__ __align__(16) __nv_bfloat16 g_hh[N_NODES_MAX * HID_DIM];
__device__ __align__(16) __nv_bfloat16 g_hl[N_NODES_MAX * HID_DIM];
__device__ __align__(16) __nv_bfloat16 g_Benc[KP * HID_DIM];
__device__ __align__(16) __nv_bfloat16 g_Bdec[KP * OUT_DIM];
__device__ __align__(16) float g_hfb[N_NODES_MAX * HID_DIM];

// --------------------------- asm helpers -----------------------------------
__device__ __forceinline__ uint32_t smem_u32(const void* p) {
    uint32_t a;
    asm("{ .reg .u64 t; cvta.to.shared.u64 t, %1; cvt.u32.u64 %0, t; }"
        : "=r"(a) : "l"(p));
    return a;
}
__device__ __forceinline__ void cp16(uint32_t dst, const void* src, uint32_t srcsize) {
    asm volatile("cp.async.cg.shared.global [%0], [%1], 16, %2;"
                 :: "r"(dst), "l"(src), "r"(srcsize) : "memory");
}
__device__ __forceinline__ void cp_commit() {
    asm volatile("cp.async.commit_group;" ::: "memory");
}
template <int N>
__device__ __forceinline__ void cp_wait() {
    asm volatile("cp.async.wait_group %0;" :: "n"(N) : "memory");
}
#define LDSM_X4(r0, r1, r2, r3, a) \
    asm volatile("ldmatrix.sync.aligned.m8n8.x4.shared.b16 {%0,%1,%2,%3}, [%4];" \
                 : "=r"(r0), "=r"(r1), "=r"(r2), "=r"(r3) : "r"(a))
#define LDSM_X4_T(r0, r1, r2, r3, a) \
    asm volatile("ldmatrix.sync.aligned.m8n8.x4.trans.shared.b16 {%0,%1,%2,%3}, [%4];" \
                 : "=r"(r0), "=r"(r1), "=r"(r2), "=r"(r3) : "r"(a))
#define MMA16816(c, a0, a1, a2, a3, b0, b1) \
    asm volatile("mma.sync.aligned.m16n8k16.row.col.f32.bf16.bf16.f32 " \
                 "{%0,%1,%2,%3}, {%4,%5,%6,%7}, {%8,%9}, {%0,%1,%2,%3};" \
                 : "+f"((c)[0]), "+f"((c)[1]), "+f"((c)[2]), "+f"((c)[3]) \
                 : "r"(a0), "r"(a1), "r"(a2), "r"(a3), "r"(b0), "r"(b1))

// ----------------------------- prep kernels --------------------------------
__global__ void prep0_kernel(const float* __restrict__ x, int M) {
    int i = blockIdx.x * blockDim.x + threadIdx.x;
    if (i >= M * IN_DIM) return;
    g_neigh[i] = 0.f;
    int r = i >> 8, c = i & 255;
    float v = x[i];
    __nv_bfloat16 hi = __float2bfloat16(v);
    g_eAh[(size_t)r * 512 + c] = hi;
    g_eAl[(size_t)r * 512 + c] = __float2bfloat16(v - __bfloat162float(hi));
    if (i < M) g_deg[i] = 0.f;
}

__global__ void scatter_kernel(const float* __restrict__ x,
                               const int* __restrict__ src,
                               const int* __restrict__ dst,
                               int n_edges) {
    const int CH = IN_DIM / 4;
    long long total = (long long)n_edges * CH;
    long long i = (long long)blockIdx.x * blockDim.x + threadIdx.x;
    if (i >= total) return;
    int e = (int)(i >> 6), c = (int)(i & 63);
    int s = src[e], d = dst[e];
    if (c == 0) atomicAdd(&g_deg[d], 1.0f);
    float4 v = reinterpret_cast<const float4*>(x)[(long long)s * CH + c];
    atomicAdd(reinterpret_cast<float4*>(g_neigh) + (long long)d * CH + c, v);
}

__global__ void prep1_kernel(const float* __restrict__ Wself,
                             const float* __restrict__ Wneigh,
                             const float* __restrict__ Wdec, int M) {
    int i = blockIdx.x * blockDim.x + threadIdx.x;
    int nx = M * IN_DIM;
    if (i < nx) {
        int r = i >> 8, c = i & 255;
        float v = g_neigh[i] / fmaxf(g_deg[r], 1.0f);
        __nv_bfloat16 hi = __float2bfloat16(v);
        g_eAh[(size_t)r * 512 + 256 + c] = hi;
        g_eAl[(size_t)r * 512 + 256 + c] = __float2bfloat16(v - __bfloat162float(hi));
        return;
    }
    int j = i - nx;
    if (j < KP * HID_DIM) {
        int kp = j >> 9, n = j & 511;
        int seg = kp >> 9, k = kp & 511;
        float w = (k < 256) ? Wself[k * HID_DIM + n] : Wneigh[(k - 256) * HID_DIM + n];
        __nv_bfloat16 hi = __float2bfloat16(w);
        g_Benc[j] = (seg == 1) ? __float2bfloat16(w - __bfloat162float(hi)) : hi;
        return;
    }
    j -= KP * HID_DIM;
    if (j < KP * OUT_DIM) {
        int kp = j >> 8, n = j & 255;
        int seg = kp >> 9, k = kp & 511;
        float w = Wdec[k * OUT_DIM + n];
        __nv_bfloat16 hi = __float2bfloat16(w);
        g_Bdec[j] = (seg == 1) ? __float2bfloat16(w - __bfloat162float(hi)) : hi;
    }
}

// ----------------------------- mma GEMM ------------------------------------
// CTA 128x128, 8 warps (4M x 2N), warp 32x64, BK=32, 3-stage cp.async pipe.
// A' segments over K' = [Ah@Bhi | Ah@Blo | Al@Bhi], A stride 512.
#define A_PITCH 80
#define B_PITCH 272
#define SZA (128 * A_PITCH)   // 10240 B
#define SZB (32 * B_PITCH)    // 8704 B
#define STAGES 3
#define SMEM_DYN (STAGES * (SZA + SZB))   // 56832 B

template <bool RELU, bool SPLIT>
__global__ __launch_bounds__(256, 2)
void gemm_mma(const __nv_bfloat16* __restrict__ Ah,
              const __nv_bfloat16* __restrict__ Al,
              const __nv_bfloat16* __restrict__ Bp,
              const float* __restrict__ bias,
              float* __restrict__ C,
              __nv_bfloat16* __restrict__ oH, __nv_bfloat16* __restrict__ oL,
              int M, int N) {
    extern __shared__ __align__(16) unsigned char smem[];
    uint32_t sA = smem_u32(smem);                 // 3 A buffers
    uint32_t sB = sA + STAGES * SZA;              // 3 B buffers

    int tid = threadIdx.x;
    int wid = tid >> 5, lane = tid & 31;
    int wm = wid & 3, wn = wid >> 2;
    int rowBase = blockIdx.y * 128;
    int colBase = blockIdx.x * 128;

    float c[2][8][4];
#pragma unroll
    for (int f = 0; f < 2; f++)
#pragma unroll
        for (int nf = 0; nf < 8; nf++)
#pragma unroll
            for (int q = 0; q < 4; q++) c[f][nf][q] = 0.f;

    auto load_chunk = [&](int buf, int ch) {
        int seg = ch >> 4;                        // 16 chunks per 512-seg
        const __nv_bfloat16* Asel = (seg < 2) ? Ah : Al;
        int k0 = (ch * 32) & 511;
        int kp0 = ch * 32;
#pragma unroll
        for (int i = 0; i < 2; i++) {
            int idx = tid + i * 256;
            int r = idx >> 2, cs = idx & 3;
            int grow = rowBase + r;
            int srow = grow < M ? grow : M - 1;
            cp16(sA + buf * SZA + r * A_PITCH + cs * 16,
                 Asel + (size_t)srow * 512 + k0 + cs * 8,
                 grow < M ? 16u : 0u);
        }
#pragma unroll
        for (int i = 0; i < 2; i++) {
            int idx = tid + i * 256;
            int r = idx >> 4, cs = idx & 15;
            cp16(sB + buf * SZB + r * B_PITCH + cs * 16,
                 Bp + (size_t)(kp0 + r) * N + colBase + cs * 8, 16u);
        }
        cp_commit();
    };

    uint32_t aAddr = sA + (wm * 32 + (lane & 15)) * A_PITCH + (lane >> 4) * 16;
    uint32_t bAddr = sB + (lane & 15) * B_PITCH + wn * 128 + (lane >> 4) * 16;

    // prologue: stages 0,1
    load_chunk(0, 0);
    load_chunk(1, 1);

    for (int ch = 0; ch < NCH; ch++) {
        int buf = ch % STAGES;
        if (ch == NCH - 1) cp_wait<0>();
        else               cp_wait<1>();
        __syncthreads();
        // issue loads for stage ch+2 (overwrites buffer of ch-1: safe post-sync)
        if (ch + 2 < NCH) load_chunk((ch + 2) % STAGES, ch + 2);

        uint32_t aB = aAddr + buf * SZA;
        uint32_t bB = bAddr + buf * SZB;
#pragma unroll
        for (int kk = 0; kk < 2; kk++) {
            uint32_t a[8];
            LDSM_X4(a[0], a[1], a[2], a[3], aB + kk * 32);
            LDSM_X4(a[4], a[5], a[6], a[7], aB + kk * 32 + 16 * A_PITCH);
            uint32_t b[16];
#pragma unroll
            for (int p = 0; p < 4; p++)
                LDSM_X4_T(b[4 * p], b[4 * p + 1], b[4 * p + 2], b[4 * p + 3],
                          bB + kk * 16 * B_PITCH + p * 32);
#pragma unroll
            for (int f = 0; f < 2; f++)
#pragma unroll
                for (int nf = 0; nf < 8; nf++) {
                    uint32_t* bp = b + (nf >> 1) * 4 + (nf & 1) * 2;
                    MMA16816(c[f][nf], a[f * 4], a[f * 4 + 1], a[f * 4 + 2],
                             a[f * 4 + 3], bp[0], bp[1]);
                }
        }
    }

    // ---- epilogue ----
    int groupID = lane >> 2, tid4 = lane & 3;
#pragma unroll
    for (int f = 0; f < 2; f++) {
        int r0 = rowBase + wm * 32 + f * 16 + groupID;
#pragma unroll
        for (int nf = 0; nf < 8; nf++) {
            int cb = colBase + wn * 64 + nf * 8 + tid4 * 2;
            float b0 = bias[cb], b1 = bias[cb + 1];
#pragma unroll
            for (int h = 0; h < 2; h++) {
                int r = r0 + h * 8;
                if (r >= M) continue;
                float v0 = c[f][nf][2 * h + 0] + b0;
                float v1 = c[f][nf][2 * h + 1] + b1;
                if (RELU) { v0 = fmaxf(v0, 0.f); v1 = fmaxf(v1, 0.f); }
                *reinterpret_cast<float2*>(C + (size_t)r * N + cb) =
                    make_float2(v0, v1);
                if (SPLIT) {
                    __nv_bfloat16 h0 = __float2bfloat16(v0);
                    __nv_bfloat16 h1 = __float2bfloat16(v1);
                    __nv_bfloat162 hv; hv.x = h0; hv.y = h1;
                    *reinterpret_cast<__nv_bfloat162*>(oH + (size_t)r * N + cb) = hv;
                    __nv_bfloat162 lv;
                    lv.x = __float2bfloat16(v0 - __bfloat162float(h0));
                    lv.y = __float2bfloat16(v1 - __bfloat162float(h1));
                    *reinterpret_cast<__nv_bfloat162*>(oL + (size_t)r * N + cb) = lv;
                }
            }
        }
    }
}

// ------------------------------ launch -------------------------------------
extern "C" void kernel_launch(void* const* d_in, const int* in_sizes, int n_in,
                              void* d_out, int out_size) {
    const float* x       = (const float*)d_in[0];
    const int*   src     = (const int*)d_in[1];
    const int*   dst     = (const int*)d_in[2];
    const float* W_self  = (const float*)d_in[3];
    const float* W_neigh = (const float*)d_in[4];
    const float* b_enc   = (const float*)d_in[5];
    const float* W_dec   = (const float*)d_in[6];
    const float* b_dec   = (const float*)d_in[7];

    int M  = in_sizes[0] / IN_DIM;
    int nE = in_sizes[1];

    float* out = (float*)d_out;
    float* h;
    if (out_size == M * (OUT_DIM + HID_DIM)) {
        h = out + (long long)M * OUT_DIM;
    } else {
        void* p = nullptr;
        cudaGetSymbolAddress(&p, g_hfb);
        h = (float*)p;
    }

    void *p_eAh, *p_eAl, *p_hh, *p_hl, *p_be, *p_bd;
    cudaGetSymbolAddress(&p_eAh, g_eAh); cudaGetSymbolAddress(&p_eAl, g_eAl);
    cudaGetSymbolAddress(&p_hh, g_hh);   cudaGetSymbolAddress(&p_hl, g_hl);
    cudaGetSymbolAddress(&p_be, g_Benc); cudaGetSymbolAddress(&p_bd, g_Bdec);

    cudaFuncSetAttribute(gemm_mma<true, true>,
                         cudaFuncAttributeMaxDynamicSharedMemorySize, SMEM_DYN);
    cudaFuncSetAttribute(gemm_mma<false, false>,
                         cudaFuncAttributeMaxDynamicSharedMemorySize, SMEM_DYN);

    // 1) zero neigh/deg + split x into combined A
    prep0_kernel<<<(M * IN_DIM + 255) / 256, 256>>>(x, M);
    // 2) scatter (degree fused)
    {
        long long items = (long long)nE * (IN_DIM / 4);
        scatter_kernel<<<(int)((items + 255) / 256), 256>>>(x, src, dst, nE);
    }
    // 3) neigh-mean split + weight packing
    {
        int total = M * IN_DIM + KP * HID_DIM + KP * OUT_DIM;
        prep1_kernel<<<(total + 255) / 256, 256>>>(W_self, W_neigh, W_dec, M);
    }
    // 4) encoder GEMM: h = relu(A' @ Benc + b_enc), emit h hi/lo
    {
        dim3 grid(HID_DIM / 128, (M + 127) / 128);
        gemm_mma<true, true><<<grid, 256, SMEM_DYN>>>(
            (const __nv_bfloat16*)p_eAh, (const __nv_bfloat16*)p_eAl,
            (const __nv_bfloat16*)p_be, b_enc, h,
            (__nv_bfloat16*)p_hh, (__nv_bfloat16*)p_hl, M, HID_DIM);
    }
    // 5) decoder GEMM: out = h' @ Bdec + b_dec
    {
        dim3 grid(OUT_DIM / 128, (M + 127) / 128);
        gemm_mma<false, false><<<grid, 256, SMEM_DYN>>>(
            (const __nv_bfloat16*)p_hh, (const __nv_bfloat16*)p_hl,
            (const __nv_bfloat16*)p_bd, b_dec, out,
            nullptr, nullptr, M, OUT_DIM);
    }
}

// round 6
// speedup vs baseline: 1.1433x; 1.0367x over previous
#include <cuda_runtime.h>
#include <cuda_bf16.h>
#include <cstdint>

// ---------------------------------------------------------------------------
// GraphAutoencoder (sm_100 base): scatter-mean -> encoder GEMM -> decoder GEMM
// R6: GEMM warp tile 64x64 (4 warps / CTA 128x128), 3-stage cp.async pipe.
// bf16 two-term split (hh, h*lo, lo*h), fp32 acc, K'=1536.
// ---------------------------------------------------------------------------

#define N_NODES_MAX 50000
#define IN_DIM      256
#define HID_DIM     512
#define OUT_DIM     256
#define KP          1536
#define NCH         48           // KP / 32

// ------------------------------ scratch ------------------------------------
__device__ __align__(16) float g_neigh[N_NODES_MAX * IN_DIM];
__device__ float g_deg[N_NODES_MAX];
__device__ __align__(16) __nv_bfloat16 g_eAh[N_NODES_MAX * 512];   // [x | nmean] hi
__device__ __align__(16) __nv_bfloat16 g_eAl[N_NODES_MAX * 512];   // [x | nmean] lo
__device__ __align__(16) __nv_bfloat16 g_hh[N_NODES_MAX * HID_DIM];
__device__ __align__(16) __nv_bfloat16 g_hl[N_NODES_MAX * HID_DIM];
__device__ __align__(16) __nv_bfloat16 g_Benc[KP * HID_DIM];
__device__ __align__(16) __nv_bfloat16 g_Bdec[KP * OUT_DIM];
__device__ __align__(16) float g_hfb[N_NODES_MAX * HID_DIM];

// --------------------------- asm helpers -----------------------------------
__device__ __forceinline__ uint32_t smem_u32(const void* p) {
    uint32_t a;
    asm("{ .reg .u64 t; cvta.to.shared.u64 t, %1; cvt.u32.u64 %0, t; }"
        : "=r"(a) : "l"(p));
    return a;
}
__device__ __forceinline__ void cp16(uint32_t dst, const void* src, uint32_t srcsize) {
    asm volatile("cp.async.cg.shared.global [%0], [%1], 16, %2;"
                 :: "r"(dst), "l"(src), "r"(srcsize) : "memory");
}
__device__ __forceinline__ void cp_commit() {
    asm volatile("cp.async.commit_group;" ::: "memory");
}
template <int N>
__device__ __forceinline__ void cp_wait() {
    asm volatile("cp.async.wait_group %0;" :: "n"(N) : "memory");
}
#define LDSM_X4(r0, r1, r2, r3, a) \
    asm volatile("ldmatrix.sync.aligned.m8n8.x4.shared.b16 {%0,%1,%2,%3}, [%4];" \
                 : "=r"(r0), "=r"(r1), "=r"(r2), "=r"(r3) : "r"(a))
#define LDSM_X4_T(r0, r1, r2, r3, a) \
    asm volatile("ldmatrix.sync.aligned.m8n8.x4.trans.shared.b16 {%0,%1,%2,%3}, [%4];" \
                 : "=r"(r0), "=r"(r1), "=r"(r2), "=r"(r3) : "r"(a))
#define MMA16816(c, a0, a1, a2, a3, b0, b1) \
    asm volatile("mma.sync.aligned.m16n8k16.row.col.f32.bf16.bf16.f32 " \
                 "{%0,%1,%2,%3}, {%4,%5,%6,%7}, {%8,%9}, {%0,%1,%2,%3};" \
                 : "+f"((c)[0]), "+f"((c)[1]), "+f"((c)[2]), "+f"((c)[3]) \
                 : "r"(a0), "r"(a1), "r"(a2), "r"(a3), "r"(b0), "r"(b1))

// ----------------------------- prep kernels --------------------------------
__global__ void prep0_kernel(const float* __restrict__ x, int M) {
    int i = blockIdx.x * blockDim.x + threadIdx.x;
    if (i >= M * IN_DIM) return;
    g_neigh[i] = 0.f;
    int r = i >> 8, c = i & 255;
    float v = x[i];
    __nv_bfloat16 hi = __float2bfloat16(v);
    g_eAh[(size_t)r * 512 + c] = hi;
    g_eAl[(size_t)r * 512 + c] = __float2bfloat16(v - __bfloat162float(hi));
    if (i < M) g_deg[i] = 0.f;
}

__global__ void scatter_kernel(const float* __restrict__ x,
                               const int* __restrict__ src,
                               const int* __restrict__ dst,
                               int n_edges) {
    const int CH = IN_DIM / 4;
    long long total = (long long)n_edges * CH;
    long long i = (long long)blockIdx.x * blockDim.x + threadIdx.x;
    if (i >= total) return;
    int e = (int)(i >> 6), c = (int)(i & 63);
    int s = src[e], d = dst[e];
    if (c == 0) atomicAdd(&g_deg[d], 1.0f);
    float4 v = reinterpret_cast<const float4*>(x)[(long long)s * CH + c];
    atomicAdd(reinterpret_cast<float4*>(g_neigh) + (long long)d * CH + c, v);
}

__global__ void prep1_kernel(const float* __restrict__ Wself,
                             const float* __restrict__ Wneigh,
                             const float* __restrict__ Wdec, int M) {
    int i = blockIdx.x * blockDim.x + threadIdx.x;
    int nx = M * IN_DIM;
    if (i < nx) {
        int r = i >> 8, c = i & 255;
        float v = g_neigh[i] / fmaxf(g_deg[r], 1.0f);
        __nv_bfloat16 hi = __float2bfloat16(v);
        g_eAh[(size_t)r * 512 + 256 + c] = hi;
        g_eAl[(size_t)r * 512 + 256 + c] = __float2bfloat16(v - __bfloat162float(hi));
        return;
    }
    int j = i - nx;
    if (j < KP * HID_DIM) {
        int kp = j >> 9, n = j & 511;
        int seg = kp >> 9, k = kp & 511;
        float w = (k < 256) ? Wself[k * HID_DIM + n] : Wneigh[(k - 256) * HID_DIM + n];
        __nv_bfloat16 hi = __float2bfloat16(w);
        g_Benc[j] = (seg == 1) ? __float2bfloat16(w - __bfloat162float(hi)) : hi;
        return;
    }
    j -= KP * HID_DIM;
    if (j < KP * OUT_DIM) {
        int kp = j >> 8, n = j & 255;
        int seg = kp >> 9, k = kp & 511;
        float w = Wdec[k * OUT_DIM + n];
        __nv_bfloat16 hi = __float2bfloat16(w);
        g_Bdec[j] = (seg == 1) ? __float2bfloat16(w - __bfloat162float(hi)) : hi;
    }
}

// ----------------------------- mma GEMM ------------------------------------
// CTA 128x128, 4 warps (2M x 2N), warp tile 64x64, BK=32, 3-stage pipe.
#define A_PITCH 80
#define B_PITCH 272
#define SZA (128 * A_PITCH)   // 10240 B
#define SZB (32 * B_PITCH)    // 8704 B
#define STAGES 3
#define SMEM_DYN (STAGES * (SZA + SZB))   // 56832 B

template <bool RELU, bool SPLIT>
__global__ __launch_bounds__(128, 2)
void gemm_mma(const __nv_bfloat16* __restrict__ Ah,
              const __nv_bfloat16* __restrict__ Al,
              const __nv_bfloat16* __restrict__ Bp,
              const float* __restrict__ bias,
              float* __restrict__ C,
              __nv_bfloat16* __restrict__ oH, __nv_bfloat16* __restrict__ oL,
              int M, int N) {
    extern __shared__ __align__(16) unsigned char smem[];
    uint32_t sA = smem_u32(smem);
    uint32_t sB = sA + STAGES * SZA;

    int tid = threadIdx.x;
    int wid = tid >> 5, lane = tid & 31;
    int wm = wid & 1, wn = wid >> 1;            // 2 x 2 warps, 64x64 tiles
    int rowBase = blockIdx.y * 128;
    int colBase = blockIdx.x * 128;

    float c[4][8][4];
#pragma unroll
    for (int mf = 0; mf < 4; mf++)
#pragma unroll
        for (int nf = 0; nf < 8; nf++)
#pragma unroll
            for (int q = 0; q < 4; q++) c[mf][nf][q] = 0.f;

    auto load_chunk = [&](int buf, int ch) {
        int seg = ch >> 4;
        const __nv_bfloat16* Asel = (seg < 2) ? Ah : Al;
        int k0 = (ch * 32) & 511;
        int kp0 = ch * 32;
#pragma unroll
        for (int i = 0; i < 4; i++) {           // A: 512 cp16 over 128 threads
            int idx = tid + i * 128;
            int r = idx >> 2, cs = idx & 3;
            int grow = rowBase + r;
            int srow = grow < M ? grow : M - 1;
            cp16(sA + buf * SZA + r * A_PITCH + cs * 16,
                 Asel + (size_t)srow * 512 + k0 + cs * 8,
                 grow < M ? 16u : 0u);
        }
#pragma unroll
        for (int i = 0; i < 4; i++) {           // B: 512 cp16
            int idx = tid + i * 128;
            int r = idx >> 4, cs = idx & 15;
            cp16(sB + buf * SZB + r * B_PITCH + cs * 16,
                 Bp + (size_t)(kp0 + r) * N + colBase + cs * 8, 16u);
        }
        cp_commit();
    };

    uint32_t aAddr = sA + (wm * 64 + (lane & 15)) * A_PITCH + (lane >> 4) * 16;
    uint32_t bAddr = sB + (lane & 15) * B_PITCH + wn * 128 + (lane >> 4) * 16;

    load_chunk(0, 0);
    load_chunk(1, 1);

    for (int ch = 0; ch < NCH; ch++) {
        int buf = ch % STAGES;
        if (ch == NCH - 1) cp_wait<0>();
        else               cp_wait<1>();
        __syncthreads();
        if (ch + 2 < NCH) load_chunk((ch + 2) % STAGES, ch + 2);

        uint32_t aB = aAddr + buf * SZA;
        uint32_t bB = bAddr + buf * SZB;
#pragma unroll
        for (int kk = 0; kk < 2; kk++) {
            uint32_t a[16];
#pragma unroll
            for (int g = 0; g < 4; g++)
                LDSM_X4(a[4 * g], a[4 * g + 1], a[4 * g + 2], a[4 * g + 3],
                        aB + g * 16 * A_PITCH + kk * 32);
            uint32_t b[16];
#pragma unroll
            for (int p = 0; p < 4; p++)
                LDSM_X4_T(b[4 * p], b[4 * p + 1], b[4 * p + 2], b[4 * p + 3],
                          bB + kk * 16 * B_PITCH + p * 32);
#pragma unroll
            for (int mf = 0; mf < 4; mf++)
#pragma unroll
                for (int nf = 0; nf < 8; nf++) {
                    uint32_t* bp = b + (nf >> 1) * 4 + (nf & 1) * 2;
                    MMA16816(c[mf][nf], a[4 * mf], a[4 * mf + 1],
                             a[4 * mf + 2], a[4 * mf + 3], bp[0], bp[1]);
                }
        }
    }

    // ---- epilogue ----
    int groupID = lane >> 2, tid4 = lane & 3;
#pragma unroll
    for (int mf = 0; mf < 4; mf++) {
        int r0 = rowBase + wm * 64 + mf * 16 + groupID;
#pragma unroll
        for (int nf = 0; nf < 8; nf++) {
            int cb = colBase + wn * 64 + nf * 8 + tid4 * 2;
            float b0 = bias[cb], b1 = bias[cb + 1];
#pragma unroll
            for (int hh = 0; hh < 2; hh++) {
                int r = r0 + hh * 8;
                if (r >= M) continue;
                float v0 = c[mf][nf][2 * hh + 0] + b0;
                float v1 = c[mf][nf][2 * hh + 1] + b1;
                if (RELU) { v0 = fmaxf(v0, 0.f); v1 = fmaxf(v1, 0.f); }
                *reinterpret_cast<float2*>(C + (size_t)r * N + cb) =
                    make_float2(v0, v1);
                if (SPLIT) {
                    __nv_bfloat16 h0 = __float2bfloat16(v0);
                    __nv_bfloat16 h1 = __float2bfloat16(v1);
                    __nv_bfloat162 hv; hv.x = h0; hv.y = h1;
                    *reinterpret_cast<__nv_bfloat162*>(oH + (size_t)r * N + cb) = hv;
                    __nv_bfloat162 lv;
                    lv.x = __float2bfloat16(v0 - __bfloat162float(h0));
                    lv.y = __float2bfloat16(v1 - __bfloat162float(h1));
                    *reinterpret_cast<__nv_bfloat162*>(oL + (size_t)r * N + cb) = lv;
                }
            }
        }
    }
}

// ------------------------------ launch -------------------------------------
extern "C" void kernel_launch(void* const* d_in, const int* in_sizes, int n_in,
                              void* d_out, int out_size) {
    const float* x       = (const float*)d_in[0];
    const int*   src     = (const int*)d_in[1];
    const int*   dst     = (const int*)d_in[2];
    const float* W_self  = (const float*)d_in[3];
    const float* W_neigh = (const float*)d_in[4];
    const float* b_enc   = (const float*)d_in[5];
    const float* W_dec   = (const float*)d_in[6];
    const float* b_dec   = (const float*)d_in[7];

    int M  = in_sizes[0] / IN_DIM;
    int nE = in_sizes[1];

    float* out = (float*)d_out;
    float* h;
    if (out_size == M * (OUT_DIM + HID_DIM)) {
        h = out + (long long)M * OUT_DIM;
    } else {
        void* p = nullptr;
        cudaGetSymbolAddress(&p, g_hfb);
        h = (float*)p;
    }

    void *p_eAh, *p_eAl, *p_hh, *p_hl, *p_be, *p_bd;
    cudaGetSymbolAddress(&p_eAh, g_eAh); cudaGetSymbolAddress(&p_eAl, g_eAl);
    cudaGetSymbolAddress(&p_hh, g_hh);   cudaGetSymbolAddress(&p_hl, g_hl);
    cudaGetSymbolAddress(&p_be, g_Benc); cudaGetSymbolAddress(&p_bd, g_Bdec);

    cudaFuncSetAttribute(gemm_mma<true, true>,
                         cudaFuncAttributeMaxDynamicSharedMemorySize, SMEM_DYN);
    cudaFuncSetAttribute(gemm_mma<false, false>,
                         cudaFuncAttributeMaxDynamicSharedMemorySize, SMEM_DYN);

    // 1) zero neigh/deg + split x into combined A
    prep0_kernel<<<(M * IN_DIM + 255) / 256, 256>>>(x, M);
    // 2) scatter (degree fused)
    {
        long long items = (long long)nE * (IN_DIM / 4);
        scatter_kernel<<<(int)((items + 255) / 256), 256>>>(x, src, dst, nE);
    }
    // 3) neigh-mean split + weight packing
    {
        int total = M * IN_DIM + KP * HID_DIM + KP * OUT_DIM;
        prep1_kernel<<<(total + 255) / 256, 256>>>(W_self, W_neigh, W_dec, M);
    }
    // 4) encoder GEMM: h = relu(A' @ Benc + b_enc), emit h hi/lo
    {
        dim3 grid(HID_DIM / 128, (M + 127) / 128);
        gemm_mma<true, true><<<grid, 128, SMEM_DYN>>>(
            (const __nv_bfloat16*)p_eAh, (const __nv_bfloat16*)p_eAl,
            (const __nv_bfloat16*)p_be, b_enc, h,
            (__nv_bfloat16*)p_hh, (__nv_bfloat16*)p_hl, M, HID_DIM);
    }
    // 5) decoder GEMM: out = h' @ Bdec + b_dec
    {
        dim3 grid(OUT_DIM / 128, (M + 127) / 128);
        gemm_mma<false, false><<<grid, 128, SMEM_DYN>>>(
            (const __nv_bfloat16*)p_hh, (const __nv_bfloat16*)p_hl,
            (const __nv_bfloat16*)p_bd, b_dec, out,
            nullptr, nullptr, M, OUT_DIM);
    }
}